// round 9
// baseline (speedup 1.0000x reference)
#include <cuda_runtime.h>
#include <cstddef>

#define TSTEPS 512
#define BATCH  512
#define NUDIM  64
#define NXDIM  128
#define NVDIM  256
#define NYDIM  64
#define RPC    4
#define NCTA   128
#define NTHR   512

// ---------------- packed transposed weights (built once per launch) ----------
// W4[k4 * J + j].q = W[j][4*k4 + q]   (J outputs, K contraction)
__device__ float4 g_C1T4 [32 * NVDIM];
__device__ float4 g_D12T4[16 * NVDIM];
__device__ float4 g_D22T4[16 * NYDIM];
__device__ float4 g_AT4  [32 * NXDIM];
__device__ float4 g_B1T4 [64 * NXDIM];
__device__ float4 g_B2T4 [16 * NXDIM];
__device__ float4 g_C2T4 [32 * NYDIM];
__device__ float4 g_D21T4[64 * NYDIM];
__device__ float4 g_D11P [64 * NVDIM];      // packed D11[j][k] over k (off-diag)
__device__ float  g_D11T [NVDIM * NVDIM];   // (kept for prep simplicity)

__global__ void prep_kernel(const float* __restrict__ A,  const float* __restrict__ B1,
                            const float* __restrict__ B2, const float* __restrict__ C1,
                            const float* __restrict__ C2, const float* __restrict__ D11,
                            const float* __restrict__ D12,const float* __restrict__ D21,
                            const float* __restrict__ D22)
{
    int id = blockIdx.x * blockDim.x + threadIdx.x;
    int off = 0;
#define XP4(dst, src, J, K)                                                  \
    if (id < off + (J) * (K) / 4) {                                          \
        int i = id - off; int k4 = i / (J); int j = i % (J);                 \
        const float* p = (src) + (size_t)j * (K) + 4 * k4;                   \
        dst[i] = make_float4(p[0], p[1], p[2], p[3]); return;                \
    } off += (J) * (K) / 4;
    XP4(g_C1T4,  C1,  NVDIM, NXDIM)
    XP4(g_D12T4, D12, NVDIM, NUDIM)
    XP4(g_D22T4, D22, NYDIM, NUDIM)
    XP4(g_AT4,   A,   NXDIM, NXDIM)
    XP4(g_B1T4,  B1,  NXDIM, NVDIM)
    XP4(g_B2T4,  B2,  NXDIM, NUDIM)
    XP4(g_C2T4,  C2,  NYDIM, NXDIM)
    XP4(g_D21T4, D21, NYDIM, NVDIM)
    XP4(g_D11P,  D11, NVDIM, NVDIM)
#undef XP4
    if (id < off + NVDIM * NVDIM) {
        int i = id - off; int k = i / NVDIM; int j = i % NVDIM;
        g_D11T[i] = D11[(size_t)j * NVDIM + k];
    }
}

// ---------------- shared memory (≈204 KB) ----------------
struct Smem {
    float4 C1T4 [32 * NVDIM];     // 128 KB staged
    float4 xk[2][NXDIM];          // state, float4 across 4 rows
    float4 w[NVDIM];              // equilibrium solution (float4 across rows)
    float4 wr4[2][128];           // per-group (w_row0,w_row1) pairs, float2[256] view
    float4 uu[2][NUDIM];          // double-buffered input tile
    float  diagc[8][4][32];       // packed 8x8 strictly-lower coefs (28 used)
    float  diagblk[8][32 * 33];   // full 32x32 diag blocks, padded rows
    float2 xslA [2][4][NXDIM];    // slack A*x partials   [group][kgroup][out]
    float2 yslC2[2][4][NYDIM];    // slack C2*x partials
    float4 xpart[3][NXDIM];       // phase-C x partials
    float4 ypart[7][NYDIM];       // phase-C y partials
};

#define FMA4C(a0,a1,a2,a3,c,v) do {                       \
    a0 = fmaf((c), (v).x, a0); a1 = fmaf((c), (v).y, a1); \
    a2 = fmaf((c), (v).z, a2); a3 = fmaf((c), (v).w, a3); } while (0)

#define GROUP_BAR(grp) asm volatile("bar.sync %0, %1;" :: "r"(1 + (grp)), "r"(256) : "memory")

__global__ void __launch_bounds__(NTHR, 1)
ren_kernel(const float* __restrict__ x0, const float* __restrict__ u,
           const float* __restrict__ D11,
           const float* __restrict__ bx, const float* __restrict__ bv,
           const float* __restrict__ by, float* __restrict__ out)
{
    extern __shared__ char smem_raw[];
    Smem& s = *reinterpret_cast<Smem*>(smem_raw);
    const int tid  = threadIdx.x;
    const int lane = tid & 31;
    const int wid  = tid >> 5;
    const int row0 = blockIdx.x * RPC;
    const int j    = tid & 255;   // owned v-feature
    const int grp  = tid >> 8;    // group = rows (2grp, 2grp+1)
    const int wg   = wid & 7;     // warp index within group == owned panel

    // ---- one-time staging ----
    for (int i = tid; i < 32 * NVDIM; i += NTHR) s.C1T4[i] = g_C1T4[i];
    if (tid < 32) {               // packed 8x8 strictly-lower blocks
        int blk = tid >> 2, g = tid & 3;
        int base = blk * 32 + g * 8, idx = 0;
        for (int ii = 1; ii < 8; ii++)
            for (int jj = 0; jj < ii; jj++)
                s.diagc[blk][g][idx++] = D11[(size_t)(base + ii) * NVDIM + (base + jj)];
    }
    for (int i = tid; i < 8 * 32 * 32; i += NTHR) {  // full diag blocks, padded
        int p = i >> 10, l = (i >> 5) & 31, q = i & 31;
        s.diagblk[p][l * 33 + q] = D11[(size_t)(32 * p + l) * NVDIM + 32 * p + q];
    }
    for (int i = tid; i < RPC * NXDIM; i += NTHR) {
        int r = i >> 7, k = i & 127;
        ((float*)s.xk[0])[k * 4 + r] = x0[(size_t)(row0 + r) * NXDIM + k];
    }
    const float bvr = bv[j];
    const float bxr = bx[tid & 127];
    const float byr = by[tid & 63];

    float ureg = 0.f;
    if (tid < 256) {
        int r = tid >> 6, k = tid & 63;
        ureg = u[((size_t)0 * BATCH + row0 + r) * NUDIM + k];
    }
    __syncthreads();

    float* yout = out + (size_t)BATCH * NXDIM;
    int cur = 0;

    for (int t = 0; t < TSTEPS; t++) {
        const int ub = t & 1;
        if (tid < 256) {
            int r = tid >> 6, k = tid & 63;
            ((float*)s.uu[ub])[k * 4 + r] = ureg;
            int tn = (t + 1 < TSTEPS) ? t + 1 : t;
            ureg = u[((size_t)tn * BATCH + row0 + r) * NUDIM + k];
        }
        __syncthreads();                         // (1) u + prev state visible
        const int nxt = cur ^ 1;
        const float4* xc = s.xk[cur];
        const float4* uc = s.uu[ub];

        // ---- phase A: b = bv + C1 x + D12 u; thread = (feature j, rows 2grp..) --
        float ba0 = bvr, ba1 = bvr;
#pragma unroll 4
        for (int k4 = 0; k4 < 32; k4++) {
            float4 c = s.C1T4[k4 * NVDIM + j];
            const float2* xp = (const float2*)&xc[4 * k4];
            float2 v0 = xp[0 + grp], v1 = xp[2 + grp], v2 = xp[4 + grp], v3 = xp[6 + grp];
            ba0 = fmaf(c.x, v0.x, ba0); ba1 = fmaf(c.x, v0.y, ba1);
            ba0 = fmaf(c.y, v1.x, ba0); ba1 = fmaf(c.y, v1.y, ba1);
            ba0 = fmaf(c.z, v2.x, ba0); ba1 = fmaf(c.z, v2.y, ba1);
            ba0 = fmaf(c.w, v3.x, ba0); ba1 = fmaf(c.w, v3.y, ba1);
        }
#pragma unroll 4
        for (int k4 = 0; k4 < 16; k4++) {
            float4 c = g_D12T4[k4 * NVDIM + j];  // streamed from L2
            const float2* up = (const float2*)&uc[4 * k4];
            float2 v0 = up[0 + grp], v1 = up[2 + grp], v2 = up[4 + grp], v3 = up[6 + grp];
            ba0 = fmaf(c.x, v0.x, ba0); ba1 = fmaf(c.x, v0.y, ba1);
            ba0 = fmaf(c.y, v1.x, ba0); ba1 = fmaf(c.y, v1.y, ba1);
            ba0 = fmaf(c.z, v2.x, ba0); ba1 = fmaf(c.z, v2.y, ba1);
            ba0 = fmaf(c.w, v3.x, ba0); ba1 = fmaf(c.w, v3.y, ba1);
        }

        // ---- phase B: owner-solves, 8 group-scoped barriers, groups desync ----
        float4 pcN[8];
#pragma unroll 1
        for (int p = 0; p < 8; p++) {
            if (wg >= p) {
                if (p > 0) {                     // apply w_{p-1} (pcN from p-1)
                    const float4* wp4 = &s.wr4[grp][16 * (p - 1)];
#pragma unroll
                    for (int g2 = 0; g2 < 8; g2++) {
                        float4 c = pcN[g2];
                        float4 wA = wp4[2 * g2], wB = wp4[2 * g2 + 1];
                        ba0 = fmaf(c.x, wA.x, ba0); ba1 = fmaf(c.x, wA.y, ba1);
                        ba0 = fmaf(c.y, wA.z, ba0); ba1 = fmaf(c.y, wA.w, ba1);
                        ba0 = fmaf(c.z, wB.x, ba0); ba1 = fmaf(c.z, wB.y, ba1);
                        ba0 = fmaf(c.w, wB.z, ba0); ba1 = fmaf(c.w, wB.w, ba1);
                    }
                }
                if (wg == p) {                   // solve panel p, BOTH rows
                    float dcl[32];
#pragma unroll
                    for (int q = 0; q < 32; q++) dcl[q] = s.diagblk[p][lane * 33 + q];
                    float bv0 = ba0, bv1 = ba1;
                    float wm0 = 0.f, wm1 = 0.f;
#pragma unroll
                    for (int gq = 0; gq < 4; gq++) {
                        const int q0 = gq * 8;
                        float cg[28];
#pragma unroll
                        for (int q = 0; q < 28; q++) cg[q] = s.diagc[p][gq][q];
                        float b0[8], b1[8];
#pragma unroll
                        for (int q = 0; q < 8; q++) {
                            b0[q] = __shfl_sync(0xffffffffu, bv0, q0 + q);
                            b1[q] = __shfl_sync(0xffffffffu, bv1, q0 + q);
                        }
                        float w0[8], w1[8];
#pragma unroll
                        for (int jj = 0; jj < 8; jj++) {     // two chains, ILP
                            float t0 = fmaxf(b0[jj], 0.f);
                            float t1 = fmaxf(b1[jj], 0.f);
                            w0[jj] = t0; w1[jj] = t1;
#pragma unroll
                            for (int ii = jj + 1; ii < 8; ii++) {
                                float c = cg[ii * (ii - 1) / 2 + jj];
                                b0[ii] = fmaf(c, t0, b0[ii]);
                                b1[ii] = fmaf(c, t1, b1[ii]);
                            }
                        }
                        if ((lane >> 3) == gq) { wm0 = w0[lane & 7]; wm1 = w1[lane & 7]; }
                        float a00 = 0.f, a01 = 0.f, a10 = 0.f, a11 = 0.f;
#pragma unroll
                        for (int jj = 0; jj < 8; jj += 2) {  // upper coefs are true 0s
                            a00 = fmaf(dcl[q0 + jj],     w0[jj],     a00);
                            a10 = fmaf(dcl[q0 + jj],     w1[jj],     a10);
                            a01 = fmaf(dcl[q0 + jj + 1], w0[jj + 1], a01);
                            a11 = fmaf(dcl[q0 + jj + 1], w1[jj + 1], a11);
                        }
                        bv0 += a00 + a01; bv1 += a10 + a11;
                    }
                    ((float2*)s.wr4[grp])[32 * p + lane] = make_float2(wm0, wm1);
                    ((float*)&s.w[32 * p + lane])[2 * grp + 0] = wm0;
                    ((float*)&s.w[32 * p + lane])[2 * grp + 1] = wm1;
                } else {                         // prefetch panel-p coefs for p+1
#pragma unroll
                    for (int g2 = 0; g2 < 8; g2++)
                        pcN[g2] = g_D11P[(p * 8 + g2) * NVDIM + j];
                }
            } else {                             // slack: A*x and C2*x slices
                int sid = p - 1 - wg;
                int id = 7 * sid - (sid * (sid - 1)) / 2 + wg;
                if (id < 16) {                   // A*x: og=id&3, kg=id>>2
                    int og = id & 3, kg = id >> 2;
                    int j2 = og * 32 + lane;
                    float a0 = 0.f, a1 = 0.f;
#pragma unroll
                    for (int i = 0; i < 8; i++) {
                        int k4 = kg * 8 + i;
                        float4 c = g_AT4[k4 * NXDIM + j2];
                        const float2* x2 = (const float2*)&xc[4 * k4];
                        float2 v0 = x2[0 + grp], v1 = x2[2 + grp], v2 = x2[4 + grp], v3 = x2[6 + grp];
                        a0 = fmaf(c.x, v0.x, a0); a1 = fmaf(c.x, v0.y, a1);
                        a0 = fmaf(c.y, v1.x, a0); a1 = fmaf(c.y, v1.y, a1);
                        a0 = fmaf(c.z, v2.x, a0); a1 = fmaf(c.z, v2.y, a1);
                        a0 = fmaf(c.w, v3.x, a0); a1 = fmaf(c.w, v3.y, a1);
                    }
                    s.xslA[grp][kg][j2] = make_float2(a0, a1);
                } else if (id < 24) {            // C2*x: og=(id-16)&1, kg=(id-16)>>1
                    int t2 = id - 16;
                    int og = t2 & 1, kg = t2 >> 1;
                    int o = og * 32 + lane;
                    float a0 = 0.f, a1 = 0.f;
#pragma unroll
                    for (int i = 0; i < 8; i++) {
                        int k4 = kg * 8 + i;
                        float4 c = g_C2T4[k4 * NYDIM + o];
                        const float2* x2 = (const float2*)&xc[4 * k4];
                        float2 v0 = x2[0 + grp], v1 = x2[2 + grp], v2 = x2[4 + grp], v3 = x2[6 + grp];
                        a0 = fmaf(c.x, v0.x, a0); a1 = fmaf(c.x, v0.y, a1);
                        a0 = fmaf(c.y, v1.x, a0); a1 = fmaf(c.y, v1.y, a1);
                        a0 = fmaf(c.z, v2.x, a0); a1 = fmaf(c.z, v2.y, a1);
                        a0 = fmaf(c.w, v3.x, a0); a1 = fmaf(c.w, v3.y, a1);
                    }
                    s.yslC2[grp][kg][o] = make_float2(a0, a1);
                }
            }
            GROUP_BAR(grp);                      // w(p) visible within group
        }
        __syncthreads();                         // (2) all w + slack visible

        // ---- phase C: x1 (B1,B2) and y (D21,D22); A,C2 done in slack ----
        const int xj = tid & 127, xq = tid >> 7;      // 4 k-chunks
        float xa0, xa1, xa2, xa3;
        xa0 = xa1 = xa2 = xa3 = (xq == 0) ? bxr : 0.f;
#pragma unroll 4
        for (int i = 0; i < 16; i++) {                // B1: 64 k per chunk
            int k4 = xq * 16 + i;
            float4 c = g_B1T4[k4 * NXDIM + xj];
            const float4* v = &s.w[4 * k4];
            FMA4C(xa0, xa1, xa2, xa3, c.x, v[0]);
            FMA4C(xa0, xa1, xa2, xa3, c.y, v[1]);
            FMA4C(xa0, xa1, xa2, xa3, c.z, v[2]);
            FMA4C(xa0, xa1, xa2, xa3, c.w, v[3]);
        }
#pragma unroll
        for (int i = 0; i < 4; i++) {                 // B2: 16 k per chunk
            int k4 = xq * 4 + i;
            float4 c = g_B2T4[k4 * NXDIM + xj];
            const float4* v = &uc[4 * k4];
            FMA4C(xa0, xa1, xa2, xa3, c.x, v[0]);
            FMA4C(xa0, xa1, xa2, xa3, c.y, v[1]);
            FMA4C(xa0, xa1, xa2, xa3, c.z, v[2]);
            FMA4C(xa0, xa1, xa2, xa3, c.w, v[3]);
        }
        if (xq > 0) s.xpart[xq - 1][xj] = make_float4(xa0, xa1, xa2, xa3);

        const int yj = tid & 63, yq = tid >> 6;       // 8 k-chunks
        float ya0, ya1, ya2, ya3;
        ya0 = ya1 = ya2 = ya3 = (yq == 0) ? byr : 0.f;
#pragma unroll 4
        for (int i = 0; i < 8; i++) {                 // D21: 32 k per chunk
            int k4 = yq * 8 + i;
            float4 c = g_D21T4[k4 * NYDIM + yj];
            const float4* v = &s.w[4 * k4];
            FMA4C(ya0, ya1, ya2, ya3, c.x, v[0]);
            FMA4C(ya0, ya1, ya2, ya3, c.y, v[1]);
            FMA4C(ya0, ya1, ya2, ya3, c.z, v[2]);
            FMA4C(ya0, ya1, ya2, ya3, c.w, v[3]);
        }
#pragma unroll
        for (int i = 0; i < 2; i++) {                 // D22: 8 k per chunk
            int k4 = yq * 2 + i;
            float4 c = g_D22T4[k4 * NYDIM + yj];
            const float4* v = &uc[4 * k4];
            FMA4C(ya0, ya1, ya2, ya3, c.x, v[0]);
            FMA4C(ya0, ya1, ya2, ya3, c.y, v[1]);
            FMA4C(ya0, ya1, ya2, ya3, c.z, v[2]);
            FMA4C(ya0, ya1, ya2, ya3, c.w, v[3]);
        }
        if (yq > 0) s.ypart[yq - 1][yj] = make_float4(ya0, ya1, ya2, ya3);
        __syncthreads();                         // (3) partials visible

        // ---- combines ----
        if (xq == 0) {
#pragma unroll
            for (int pq = 0; pq < 3; pq++) {
                float4 pp = s.xpart[pq][xj];
                xa0 += pp.x; xa1 += pp.y; xa2 += pp.z; xa3 += pp.w;
            }
#pragma unroll
            for (int kg = 0; kg < 4; kg++) {
                float2 a01 = s.xslA[0][kg][xj];
                float2 a23 = s.xslA[1][kg][xj];
                xa0 += a01.x; xa1 += a01.y; xa2 += a23.x; xa3 += a23.y;
            }
            s.xk[nxt][xj] = make_float4(xa0, xa1, xa2, xa3);
        }
        if (yq == 0) {
#pragma unroll
            for (int pq = 0; pq < 7; pq++) {
                float4 pp = s.ypart[pq][yj];
                ya0 += pp.x; ya1 += pp.y; ya2 += pp.z; ya3 += pp.w;
            }
#pragma unroll
            for (int kg = 0; kg < 4; kg++) {
                float2 c01 = s.yslC2[0][kg][yj];
                float2 c23 = s.yslC2[1][kg][yj];
                ya0 += c01.x; ya1 += c01.y; ya2 += c23.x; ya3 += c23.y;
            }
            float* yo = yout + ((size_t)t * BATCH + row0) * NYDIM + yj;
            yo[0 * NYDIM] = ya0;
            yo[1 * NYDIM] = ya1;
            yo[2 * NYDIM] = ya2;
            yo[3 * NYDIM] = ya3;
        }
        cur ^= 1;
    }

    // ---- final state x1 ----
    __syncthreads();
    if (tid < NXDIM) {
        float4 v = s.xk[cur][tid];
        out[(size_t)(row0 + 0) * NXDIM + tid] = v.x;
        out[(size_t)(row0 + 1) * NXDIM + tid] = v.y;
        out[(size_t)(row0 + 2) * NXDIM + tid] = v.z;
        out[(size_t)(row0 + 3) * NXDIM + tid] = v.w;
    }
}

extern "C" void kernel_launch(void* const* d_in, const int* in_sizes, int n_in,
                              void* d_out, int out_size)
{
    const float* x0  = (const float*)d_in[0];
    const float* u   = (const float*)d_in[1];
    const float* A   = (const float*)d_in[2];
    const float* B1  = (const float*)d_in[3];
    const float* B2  = (const float*)d_in[4];
    const float* C1  = (const float*)d_in[5];
    const float* C2  = (const float*)d_in[6];
    const float* D11 = (const float*)d_in[7];
    const float* D12 = (const float*)d_in[8];
    const float* D21 = (const float*)d_in[9];
    const float* D22 = (const float*)d_in[10];
    const float* bx  = (const float*)d_in[11];
    const float* bv  = (const float*)d_in[12];
    const float* by  = (const float*)d_in[13];
    float* out = (float*)d_out;

    prep_kernel<<<452, 256>>>(A, B1, B2, C1, C2, D11, D12, D21, D22);

    size_t smem = sizeof(Smem);
    cudaFuncSetAttribute(ren_kernel, cudaFuncAttributeMaxDynamicSharedMemorySize,
                         (int)smem);
    ren_kernel<<<NCTA, NTHR, smem>>>(x0, u, D11, bx, bv, by, out);
}

// round 10
// speedup vs baseline: 1.0829x; 1.0829x over previous
#include <cuda_runtime.h>
#include <cstddef>

#define TSTEPS 512
#define BATCH  512
#define NUDIM  64
#define NXDIM  128
#define NVDIM  256
#define NYDIM  64
#define RPC    2
#define NCTA   (BATCH / RPC)   // 256 CTAs -> 2 per SM
#define NTHR   256

// ---------------- packed transposed weights (built once per launch) ----------
// W4[k4 * J + j].q = W[j][4*k4 + q]   (J outputs, K contraction)
__device__ float4 g_C1T4 [32 * NVDIM];
__device__ float4 g_D12T4[16 * NVDIM];
__device__ float4 g_D22T4[16 * NYDIM];
__device__ float4 g_AT4  [32 * NXDIM];
__device__ float4 g_B1T4 [64 * NXDIM];
__device__ float4 g_B2T4 [16 * NXDIM];
__device__ float4 g_C2T4 [32 * NYDIM];
__device__ float4 g_D21T4[64 * NYDIM];
__device__ float4 g_D11P [64 * NVDIM];      // packed D11[j][k] over k (off-diag)
__device__ float  g_D11T [NVDIM * NVDIM];   // scalar D11T[k*256+j] = D11[j][k]

__global__ void prep_kernel(const float* __restrict__ A,  const float* __restrict__ B1,
                            const float* __restrict__ B2, const float* __restrict__ C1,
                            const float* __restrict__ C2, const float* __restrict__ D11,
                            const float* __restrict__ D12,const float* __restrict__ D21,
                            const float* __restrict__ D22)
{
    int id = blockIdx.x * blockDim.x + threadIdx.x;
    int off = 0;
#define XP4(dst, src, J, K)                                                  \
    if (id < off + (J) * (K) / 4) {                                          \
        int i = id - off; int k4 = i / (J); int j = i % (J);                 \
        const float* p = (src) + (size_t)j * (K) + 4 * k4;                   \
        dst[i] = make_float4(p[0], p[1], p[2], p[3]); return;                \
    } off += (J) * (K) / 4;
    XP4(g_C1T4,  C1,  NVDIM, NXDIM)
    XP4(g_D12T4, D12, NVDIM, NUDIM)
    XP4(g_D22T4, D22, NYDIM, NUDIM)
    XP4(g_AT4,   A,   NXDIM, NXDIM)
    XP4(g_B1T4,  B1,  NXDIM, NVDIM)
    XP4(g_B2T4,  B2,  NXDIM, NUDIM)
    XP4(g_C2T4,  C2,  NYDIM, NXDIM)
    XP4(g_D21T4, D21, NYDIM, NVDIM)
    XP4(g_D11P,  D11, NVDIM, NVDIM)
#undef XP4
    if (id < off + NVDIM * NVDIM) {
        int i = id - off; int k = i / NVDIM; int j = i % NVDIM;
        g_D11T[i] = D11[(size_t)j * NVDIM + k];
    }
}

// ---------------- shared memory (~12 KB -> 2 CTAs/SM, big L1D carveout) -------
struct Smem {
    float2 xk[2][NXDIM];          // state, float2 across the 2 rows
    float2 w[NVDIM];              // equilibrium solution
    float2 uu[2][NUDIM];          // double-buffered input tile
    float2 bblk[32];              // panel handoff
    float  diagc[8][4][32];       // packed 8x8 strictly-lower coefs (28 used)
    float2 xpart[NXDIM];         // phase-C x partial (chunk 1)
    float2 ypart[3][NYDIM];      // phase-C y partials (chunks 1..3)
};

// c: scalar coef; V01/V23: float4 = (k0.r0,k0.r1,k1.r0,k1.r1)...
#define FMA2x4(ba0, ba1, c4, V01, V23) do {                       \
    ba0 = fmaf((c4).x, (V01).x, ba0); ba1 = fmaf((c4).x, (V01).y, ba1); \
    ba0 = fmaf((c4).y, (V01).z, ba0); ba1 = fmaf((c4).y, (V01).w, ba1); \
    ba0 = fmaf((c4).z, (V23).x, ba0); ba1 = fmaf((c4).z, (V23).y, ba1); \
    ba0 = fmaf((c4).w, (V23).z, ba0); ba1 = fmaf((c4).w, (V23).w, ba1); } while (0)

__global__ void __launch_bounds__(NTHR, 2)
ren_kernel(const float* __restrict__ x0, const float* __restrict__ u,
           const float* __restrict__ D11,
           const float* __restrict__ bx, const float* __restrict__ bv,
           const float* __restrict__ by, float* __restrict__ out)
{
    extern __shared__ char smem_raw[];
    Smem& s = *reinterpret_cast<Smem*>(smem_raw);
    const int tid  = threadIdx.x;
    const int lane = tid & 31;
    const int wid  = tid >> 5;
    const int row0 = blockIdx.x * RPC;
    const int j    = tid;          // owned v-feature in phases A/B

    // ---- one-time staging ----
    if (tid < 32) {                // packed 8x8 strictly-lower diag-group coefs
        int blk = tid >> 2, g = tid & 3;
        int base = blk * 32 + g * 8, idx = 0;
        for (int ii = 1; ii < 8; ii++)
            for (int jj = 0; jj < ii; jj++)
                s.diagc[blk][g][idx++] = D11[(size_t)(base + ii) * NVDIM + (base + jj)];
    }
    if (tid < NXDIM) {             // initial state, 2 rows
        s.xk[0][tid] = make_float2(x0[(size_t)(row0 + 0) * NXDIM + tid],
                                   x0[(size_t)(row0 + 1) * NXDIM + tid]);
    }
    const float bvr = bv[j];
    const float bxr = bx[tid & 127];
    const float byr = by[tid & 63];

    float dc[32];                  // diag columns for solver warps (panel 0)
    if (wid < 2) {
#pragma unroll
        for (int q = 0; q < 32; q++)
            dc[q] = g_D11T[(size_t)q * NVDIM + lane];
    }
    float ureg = 0.f;              // prefetch u(0): threads 0-127, (row, k)
    if (tid < 2 * NUDIM) {
        int r = tid >> 6, k = tid & 63;
        ureg = u[((size_t)0 * BATCH + row0 + r) * NUDIM + k];
    }
    __syncthreads();

    float* yout = out + (size_t)BATCH * NXDIM;
    int cur = 0;

    for (int t = 0; t < TSTEPS; t++) {
        const int ub = t & 1;
        if (tid < 2 * NUDIM) {     // commit u(t), prefetch u(t+1)
            int r = tid >> 6, k = tid & 63;
            ((float*)s.uu[ub])[k * 2 + r] = ureg;
            int tn = (t + 1 < TSTEPS) ? t + 1 : t;
            ureg = u[((size_t)tn * BATCH + row0 + r) * NUDIM + k];
        }
        __syncthreads();                          // (1) u + state visible
        const int nxt = cur ^ 1;
        const float2* xc = s.xk[cur];
        const float2* uc = s.uu[ub];

        // ---- phase A: b = bv + C1 x + D12 u (thread = feature, 2 rows) ----
        float ba0 = bvr, ba1 = bvr;
#pragma unroll 4
        for (int k4 = 0; k4 < 32; k4++) {
            float4 c = g_C1T4[k4 * NVDIM + j];
            const float4* xp = (const float4*)&xc[4 * k4];
            float4 v01 = xp[0], v23 = xp[1];
            FMA2x4(ba0, ba1, c, v01, v23);
        }
#pragma unroll 4
        for (int k4 = 0; k4 < 16; k4++) {
            float4 c = g_D12T4[k4 * NVDIM + j];
            const float4* up = (const float4*)&uc[4 * k4];
            float4 v01 = up[0], v23 = up[1];
            FMA2x4(ba0, ba1, c, v01, v23);
        }

        // ---- phase B: R3-style blocked triangular ReLU equilibrium ----
        for (int p = 0; p < 8; p++) {
            const int base = p * 32;
            if (wid == p)                          // owner warp = panel warp
                s.bblk[lane] = make_float2(ba0, ba1);
            __syncthreads();                       // B1: bblk visible

            if (wid < 2) {                         // warp r solves row r
                const int r = wid;
                float bval = ((const float*)&s.bblk[lane])[r];
                float wmine = 0.f;
#pragma unroll
                for (int g = 0; g < 4; g++) {
                    const int q0 = g * 8;
                    float cg[28];
#pragma unroll
                    for (int q = 0; q < 28; q++) cg[q] = s.diagc[p][g][q];
                    float bg[8];
#pragma unroll
                    for (int q = 0; q < 8; q++)
                        bg[q] = __shfl_sync(0xffffffffu, bval, q0 + q);
                    float wloc[8];
#pragma unroll
                    for (int jj = 0; jj < 8; jj++) {   // redundant serial resolve
                        float wj = fmaxf(bg[jj], 0.f);
                        wloc[jj] = wj;
#pragma unroll
                        for (int ii = jj + 1; ii < 8; ii++)
                            bg[ii] = fmaf(cg[ii * (ii - 1) / 2 + jj], wj, bg[ii]);
                    }
                    if ((lane >> 3) == g) wmine = wloc[lane & 7];
                    float a0 = 0.f, a1 = 0.f;          // apply (upper coefs are 0)
                    a0 = fmaf(dc[q0 + 0], wloc[0], a0); a1 = fmaf(dc[q0 + 1], wloc[1], a1);
                    a0 = fmaf(dc[q0 + 2], wloc[2], a0); a1 = fmaf(dc[q0 + 3], wloc[3], a1);
                    a0 = fmaf(dc[q0 + 4], wloc[4], a0); a1 = fmaf(dc[q0 + 5], wloc[5], a1);
                    a0 = fmaf(dc[q0 + 6], wloc[6], a0); a1 = fmaf(dc[q0 + 7], wloc[7], a1);
                    bval += a0 + a1;
                }
                ((float*)&s.w[base + lane])[r] = wmine;
                const int nbase = ((p + 1) & 7) * 32;   // prefetch next diag cols
#pragma unroll
                for (int q = 0; q < 32; q++)
                    dc[q] = g_D11T[(size_t)(nbase + q) * NVDIM + (nbase + lane)];
            }
            __syncthreads();                       // B2: w(p) visible

            if (j >= base + 32) {                  // rank-32 off-diag update
                const float4* wp = (const float4*)&s.w[base];
#pragma unroll
                for (int g2 = 0; g2 < 8; g2++) {
                    float4 c = g_D11P[(p * 8 + g2) * NVDIM + j];
                    float4 wA = wp[2 * g2], wB = wp[2 * g2 + 1];
                    FMA2x4(ba0, ba1, c, wA, wB);
                }
            }
        }
        __syncthreads();                           // (2) all w visible

        // ---- phase C: x1 (A,B1,B2) and y (C2,D21,D22), k-split ----
        const int xj = tid & 127, xq = tid >> 7;      // 2 k-chunks
        float xa0, xa1;
        xa0 = xa1 = (xq == 0) ? bxr : 0.f;
#pragma unroll 4
        for (int i = 0; i < 16; i++) {                // A: 64 k per chunk
            int k4 = xq * 16 + i;
            float4 c = g_AT4[k4 * NXDIM + xj];
            const float4* v = (const float4*)&xc[4 * k4];
            float4 v01 = v[0], v23 = v[1];
            FMA2x4(xa0, xa1, c, v01, v23);
        }
#pragma unroll 4
        for (int i = 0; i < 32; i++) {                // B1: 128 k per chunk
            int k4 = xq * 32 + i;
            float4 c = g_B1T4[k4 * NXDIM + xj];
            const float4* v = (const float4*)&s.w[4 * k4];
            float4 v01 = v[0], v23 = v[1];
            FMA2x4(xa0, xa1, c, v01, v23);
        }
#pragma unroll
        for (int i = 0; i < 8; i++) {                 // B2: 32 k per chunk
            int k4 = xq * 8 + i;
            float4 c = g_B2T4[k4 * NXDIM + xj];
            const float4* v = (const float4*)&uc[4 * k4];
            float4 v01 = v[0], v23 = v[1];
            FMA2x4(xa0, xa1, c, v01, v23);
        }
        if (xq == 1) s.xpart[xj] = make_float2(xa0, xa1);

        const int yj = tid & 63, yq = tid >> 6;       // 4 k-chunks
        float ya0, ya1;
        ya0 = ya1 = (yq == 0) ? byr : 0.f;
#pragma unroll
        for (int i = 0; i < 8; i++) {                 // C2: 32 k per chunk
            int k4 = yq * 8 + i;
            float4 c = g_C2T4[k4 * NYDIM + yj];
            const float4* v = (const float4*)&xc[4 * k4];
            float4 v01 = v[0], v23 = v[1];
            FMA2x4(ya0, ya1, c, v01, v23);
        }
#pragma unroll 4
        for (int i = 0; i < 16; i++) {                // D21: 64 k per chunk
            int k4 = yq * 16 + i;
            float4 c = g_D21T4[k4 * NYDIM + yj];
            const float4* v = (const float4*)&s.w[4 * k4];
            float4 v01 = v[0], v23 = v[1];
            FMA2x4(ya0, ya1, c, v01, v23);
        }
#pragma unroll
        for (int i = 0; i < 4; i++) {                 // D22: 16 k per chunk
            int k4 = yq * 4 + i;
            float4 c = g_D22T4[k4 * NYDIM + yj];
            const float4* v = (const float4*)&uc[4 * k4];
            float4 v01 = v[0], v23 = v[1];
            FMA2x4(ya0, ya1, c, v01, v23);
        }
        if (yq > 0) s.ypart[yq - 1][yj] = make_float2(ya0, ya1);
        __syncthreads();                           // (3) partials visible

        // ---- combines ----
        if (xq == 0) {
            float2 pp = s.xpart[xj];
            xa0 += pp.x; xa1 += pp.y;
            s.xk[nxt][xj] = make_float2(xa0, xa1);
        }
        if (yq == 0) {
#pragma unroll
            for (int pq = 0; pq < 3; pq++) {
                float2 pp = s.ypart[pq][yj];
                ya0 += pp.x; ya1 += pp.y;
            }
            float* yo = yout + ((size_t)t * BATCH + row0) * NYDIM + yj;
            yo[0 * NYDIM] = ya0;
            yo[1 * NYDIM] = ya1;
        }
        cur ^= 1;
    }

    // ---- final state x1 ----
    __syncthreads();
    if (tid < NXDIM) {
        float2 v = s.xk[cur][tid];
        out[(size_t)(row0 + 0) * NXDIM + tid] = v.x;
        out[(size_t)(row0 + 1) * NXDIM + tid] = v.y;
    }
}

extern "C" void kernel_launch(void* const* d_in, const int* in_sizes, int n_in,
                              void* d_out, int out_size)
{
    const float* x0  = (const float*)d_in[0];
    const float* u   = (const float*)d_in[1];
    const float* A   = (const float*)d_in[2];
    const float* B1  = (const float*)d_in[3];
    const float* B2  = (const float*)d_in[4];
    const float* C1  = (const float*)d_in[5];
    const float* C2  = (const float*)d_in[6];
    const float* D11 = (const float*)d_in[7];
    const float* D12 = (const float*)d_in[8];
    const float* D21 = (const float*)d_in[9];
    const float* D22 = (const float*)d_in[10];
    const float* bx  = (const float*)d_in[11];
    const float* bv  = (const float*)d_in[12];
    const float* by  = (const float*)d_in[13];
    float* out = (float*)d_out;

    prep_kernel<<<452, 256>>>(A, B1, B2, C1, C2, D11, D12, D21, D22);

    size_t smem = sizeof(Smem);
    cudaFuncSetAttribute(ren_kernel, cudaFuncAttributeMaxDynamicSharedMemorySize,
                         (int)smem);
    ren_kernel<<<NCTA, NTHR, smem>>>(x0, u, D11, bx, bv, by, out);
}

// round 12
// speedup vs baseline: 1.2293x; 1.1352x over previous
#include <cuda_runtime.h>
#include <cstddef>

#define TSTEPS 512
#define BATCH  512
#define NUDIM  64
#define NXDIM  128
#define NVDIM  256
#define NYDIM  64
#define RPC    4
#define NCTA   128
#define NTHR   512

// ---------------- packed transposed weights (built once per launch) ----------
// W4[k4 * J + j].q = W[j][4*k4 + q]   (J outputs, K contraction)
__device__ float4 g_C1T4 [32 * NVDIM];
__device__ float4 g_D12T4[16 * NVDIM];
__device__ float4 g_D22T4[16 * NYDIM];
__device__ float4 g_AT4  [32 * NXDIM];
__device__ float4 g_B1T4 [64 * NXDIM];
__device__ float4 g_B2T4 [16 * NXDIM];
__device__ float4 g_C2T4 [32 * NYDIM];
__device__ float4 g_D21T4[64 * NYDIM];
__device__ float4 g_D11P [64 * NVDIM];      // packed D11[j][k] over k (off-diag)
__device__ float  g_D11T [NVDIM * NVDIM];   // scalar transpose (prep only)

__global__ void prep_kernel(const float* __restrict__ A,  const float* __restrict__ B1,
                            const float* __restrict__ B2, const float* __restrict__ C1,
                            const float* __restrict__ C2, const float* __restrict__ D11,
                            const float* __restrict__ D12,const float* __restrict__ D21,
                            const float* __restrict__ D22)
{
    int id = blockIdx.x * blockDim.x + threadIdx.x;
    int off = 0;
#define XP4(dst, src, J, K)                                                  \
    if (id < off + (J) * (K) / 4) {                                          \
        int i = id - off; int k4 = i / (J); int j = i % (J);                 \
        const float* p = (src) + (size_t)j * (K) + 4 * k4;                   \
        dst[i] = make_float4(p[0], p[1], p[2], p[3]); return;                \
    } off += (J) * (K) / 4;
    XP4(g_C1T4,  C1,  NVDIM, NXDIM)
    XP4(g_D12T4, D12, NVDIM, NUDIM)
    XP4(g_D22T4, D22, NYDIM, NUDIM)
    XP4(g_AT4,   A,   NXDIM, NXDIM)
    XP4(g_B1T4,  B1,  NXDIM, NVDIM)
    XP4(g_B2T4,  B2,  NXDIM, NUDIM)
    XP4(g_C2T4,  C2,  NYDIM, NXDIM)
    XP4(g_D21T4, D21, NYDIM, NVDIM)
    XP4(g_D11P,  D11, NVDIM, NVDIM)
#undef XP4
    if (id < off + NVDIM * NVDIM) {
        int i = id - off; int k = i / NVDIM; int j = i % NVDIM;
        g_D11T[i] = D11[(size_t)j * NVDIM + k];
    }
}

// panel start offsets (float4 units) in the packed off-diag triangle
// panel p spans rows j in [32(p+1), 256): width W_p = 224 - 32p, 8 float4-coefs each
#define OFFP0 0
#define OFFP1 1792
#define OFFP2 3328
#define OFFP3 4608
#define OFFP4 5632
#define OFFP5 6400
#define OFFP6 6912
#define OFFD_TOT 7168

// ---------------- shared memory (~176.5 KB) ----------------
struct Smem {
    float4 offd[OFFD_TOT];        // 114.7 KB packed strictly-lower off-diag D11
    float  diagblk[8][32 * 33];   //  33.8 KB padded 32x32 diag blocks
    float  diagc[8][4][32];       //   4 KB packed 8x8 strictly-lower coefs
    float4 xk[2][NXDIM];          // state, float4 across 4 rows
    float4 w[NVDIM];              // equilibrium solution
    float4 uu[2][NUDIM];          // double-buffered input tile
    float  bblk[32][4];           // panel handoff
    float4 xpart[3][NXDIM];      // phase-C x partials
    float4 ypart[7][NYDIM];      // phase-C y partials
};

#define FMA4C(a0,a1,a2,a3,c,v) do {                       \
    a0 = fmaf((c), (v).x, a0); a1 = fmaf((c), (v).y, a1); \
    a2 = fmaf((c), (v).z, a2); a3 = fmaf((c), (v).w, a3); } while (0)

__global__ void __launch_bounds__(NTHR, 1)
ren_kernel(const float* __restrict__ x0, const float* __restrict__ u,
           const float* __restrict__ D11,
           const float* __restrict__ bx, const float* __restrict__ bv,
           const float* __restrict__ by, float* __restrict__ out)
{
    extern __shared__ char smem_raw[];
    Smem& s = *reinterpret_cast<Smem*>(smem_raw);
    const int tid  = threadIdx.x;
    const int lane = tid & 31;
    const int wid  = tid >> 5;
    const int row0 = blockIdx.x * RPC;
    const int j    = tid & 255;   // v-feature owned in phases A/B
    const int h    = tid >> 8;    // row-pair selector
    const int OFFP[8] = {OFFP0, OFFP1, OFFP2, OFFP3, OFFP4, OFFP5, OFFP6, OFFD_TOT};

    // ---- one-time staging ----
    // packed off-diag triangle: panel p, layout [g2][j'] (j' = j - 32(p+1))
#pragma unroll
    for (int p = 0; p < 7; p++) {
        const int W = 224 - 32 * p;
        for (int i = tid; i < 8 * W; i += NTHR) {
            int g2 = i / W, jp = i - g2 * W;
            s.offd[OFFP[p] + i] = g_D11P[(p * 8 + g2) * NVDIM + (32 * (p + 1) + jp)];
        }
    }
    for (int i = tid; i < 8 * 32 * 32; i += NTHR) {   // padded diag blocks
        int p = i >> 10, l = (i >> 5) & 31, q = i & 31;
        s.diagblk[p][l * 33 + q] = D11[(size_t)(32 * p + l) * NVDIM + 32 * p + q];
    }
    if (tid < 32) {                 // packed 8x8 strictly-lower group coefs
        int blk = tid >> 2, g = tid & 3;
        int base = blk * 32 + g * 8, idx = 0;
        for (int ii = 1; ii < 8; ii++)
            for (int jj = 0; jj < ii; jj++)
                s.diagc[blk][g][idx++] = D11[(size_t)(base + ii) * NVDIM + (base + jj)];
    }
    for (int i = tid; i < RPC * NXDIM; i += NTHR) {   // initial state
        int r = i >> 7, k = i & 127;
        ((float*)s.xk[0])[k * 4 + r] = x0[(size_t)(row0 + r) * NXDIM + k];
    }
    const float bvr = bv[j];
    const float bxr = bx[tid & 127];
    const float byr = by[tid & 63];

    float ureg = 0.f;               // prefetch u(0)
    if (tid < 256) {
        int r = tid >> 6, k = tid & 63;
        ureg = u[((size_t)0 * BATCH + row0 + r) * NUDIM + k];
    }
    __syncthreads();

    float* yout = out + (size_t)BATCH * NXDIM;
    int cur = 0;

    for (int t = 0; t < TSTEPS; t++) {
        const int ub = t & 1;
        if (tid < 256) {            // commit u(t), prefetch u(t+1)
            int r = tid >> 6, k = tid & 63;
            ((float*)s.uu[ub])[k * 4 + r] = ureg;
            int tn = (t + 1 < TSTEPS) ? t + 1 : t;
            ureg = u[((size_t)tn * BATCH + row0 + r) * NUDIM + k];
        }
        __syncthreads();
        const int nxt = cur ^ 1;
        const float4* xc = s.xk[cur];
        const float4* uc = s.uu[ub];

        // ---- phase A: b = bv + C1 x + D12 u (weights from L2/L1D) ----
        float ba0 = bvr, ba1 = bvr;
#pragma unroll 4
        for (int k4 = 0; k4 < 32; k4++) {
            float4 c = g_C1T4[k4 * NVDIM + j];
            const float2* xp = (const float2*)&xc[4 * k4];
            float2 v0 = xp[0 + h], v1 = xp[2 + h], v2 = xp[4 + h], v3 = xp[6 + h];
            ba0 = fmaf(c.x, v0.x, ba0); ba1 = fmaf(c.x, v0.y, ba1);
            ba0 = fmaf(c.y, v1.x, ba0); ba1 = fmaf(c.y, v1.y, ba1);
            ba0 = fmaf(c.z, v2.x, ba0); ba1 = fmaf(c.z, v2.y, ba1);
            ba0 = fmaf(c.w, v3.x, ba0); ba1 = fmaf(c.w, v3.y, ba1);
        }
#pragma unroll 4
        for (int k4 = 0; k4 < 16; k4++) {
            float4 c = g_D12T4[k4 * NVDIM + j];
            const float2* up = (const float2*)&uc[4 * k4];
            float2 v0 = up[0 + h], v1 = up[2 + h], v2 = up[4 + h], v3 = up[6 + h];
            ba0 = fmaf(c.x, v0.x, ba0); ba1 = fmaf(c.x, v0.y, ba1);
            ba0 = fmaf(c.y, v1.x, ba0); ba1 = fmaf(c.y, v1.y, ba1);
            ba0 = fmaf(c.z, v2.x, ba0); ba1 = fmaf(c.z, v2.y, ba1);
            ba0 = fmaf(c.w, v3.x, ba0); ba1 = fmaf(c.w, v3.y, ba1);
        }

        // ---- phase B: blocked triangular ReLU equilibrium (all smem) ----
#pragma unroll
        for (int p = 0; p < 8; p++) {
            const int base = p * 32;
            if (j >= base && j < base + 32)
                *(float2*)&s.bblk[j - base][2 * h] = make_float2(ba0, ba1);
            __syncthreads();                       // B1: bblk visible

            if (wid < 4) {                         // warp r solves row r
                const int r = wid;
                float dcl[32];                     // conflict-free padded reads
#pragma unroll
                for (int q = 0; q < 32; q++) dcl[q] = s.diagblk[p][lane * 33 + q];
                float bval = s.bblk[lane][r];
                float wmine = 0.f;
#pragma unroll
                for (int g = 0; g < 4; g++) {
                    const int q0 = g * 8;
                    float cg[28];
#pragma unroll
                    for (int q = 0; q < 28; q++) cg[q] = s.diagc[p][g][q];
                    float bg[8];
#pragma unroll
                    for (int q = 0; q < 8; q++)
                        bg[q] = __shfl_sync(0xffffffffu, bval, q0 + q);
                    float wloc[8];
#pragma unroll
                    for (int jj = 0; jj < 8; jj++) {   // redundant serial resolve
                        float wj = fmaxf(bg[jj], 0.f);
                        wloc[jj] = wj;
#pragma unroll
                        for (int ii = jj + 1; ii < 8; ii++)
                            bg[ii] = fmaf(cg[ii * (ii - 1) / 2 + jj], wj, bg[ii]);
                    }
                    if ((lane >> 3) == g) wmine = wloc[lane & 7];
                    float a0 = 0.f, a1 = 0.f;          // apply (upper coefs are 0)
                    a0 = fmaf(dcl[q0 + 0], wloc[0], a0); a1 = fmaf(dcl[q0 + 1], wloc[1], a1);
                    a0 = fmaf(dcl[q0 + 2], wloc[2], a0); a1 = fmaf(dcl[q0 + 3], wloc[3], a1);
                    a0 = fmaf(dcl[q0 + 4], wloc[4], a0); a1 = fmaf(dcl[q0 + 5], wloc[5], a1);
                    a0 = fmaf(dcl[q0 + 6], wloc[6], a0); a1 = fmaf(dcl[q0 + 7], wloc[7], a1);
                    bval += a0 + a1;
                }
                ((float*)&s.w[base + lane])[r] = wmine;
            }
            __syncthreads();                       // B2: w(p) visible

            if (j >= base + 32) {                  // rank-32 off-diag, smem coefs
                const int W = 224 - 32 * p;
                const float4* cp = s.offd + OFFP[p] + (j - base - 32);
#pragma unroll
                for (int g2 = 0; g2 < 8; g2++) {
                    float4 c = cp[g2 * W];
                    const float2* wp = (const float2*)&s.w[base + 4 * g2];
                    float2 w0 = wp[0 + h], w1 = wp[2 + h], w2 = wp[4 + h], w3 = wp[6 + h];
                    ba0 = fmaf(c.x, w0.x, ba0); ba1 = fmaf(c.x, w0.y, ba1);
                    ba0 = fmaf(c.y, w1.x, ba0); ba1 = fmaf(c.y, w1.y, ba1);
                    ba0 = fmaf(c.z, w2.x, ba0); ba1 = fmaf(c.z, w2.y, ba1);
                    ba0 = fmaf(c.w, w3.x, ba0); ba1 = fmaf(c.w, w3.y, ba1);
                }
            }
        }

        // ---- phase C: x1 and y, k-split over thread groups ----
        const int xj = tid & 127, xq = tid >> 7;      // 4 k-chunks
        float xa0, xa1, xa2, xa3;
        xa0 = xa1 = xa2 = xa3 = (xq == 0) ? bxr : 0.f;
#pragma unroll 4
        for (int i = 0; i < 8; i++) {                 // A: 32 k per chunk
            int k4 = xq * 8 + i;
            float4 c = g_AT4[k4 * NXDIM + xj];
            const float4* v = &xc[4 * k4];
            FMA4C(xa0, xa1, xa2, xa3, c.x, v[0]);
            FMA4C(xa0, xa1, xa2, xa3, c.y, v[1]);
            FMA4C(xa0, xa1, xa2, xa3, c.z, v[2]);
            FMA4C(xa0, xa1, xa2, xa3, c.w, v[3]);
        }
#pragma unroll 4
        for (int i = 0; i < 16; i++) {                // B1: 64 k per chunk
            int k4 = xq * 16 + i;
            float4 c = g_B1T4[k4 * NXDIM + xj];
            const float4* v = &s.w[4 * k4];
            FMA4C(xa0, xa1, xa2, xa3, c.x, v[0]);
            FMA4C(xa0, xa1, xa2, xa3, c.y, v[1]);
            FMA4C(xa0, xa1, xa2, xa3, c.z, v[2]);
            FMA4C(xa0, xa1, xa2, xa3, c.w, v[3]);
        }
#pragma unroll
        for (int i = 0; i < 4; i++) {                 // B2: 16 k per chunk
            int k4 = xq * 4 + i;
            float4 c = g_B2T4[k4 * NXDIM + xj];
            const float4* v = &uc[4 * k4];
            FMA4C(xa0, xa1, xa2, xa3, c.x, v[0]);
            FMA4C(xa0, xa1, xa2, xa3, c.y, v[1]);
            FMA4C(xa0, xa1, xa2, xa3, c.z, v[2]);
            FMA4C(xa0, xa1, xa2, xa3, c.w, v[3]);
        }
        if (xq > 0) s.xpart[xq - 1][xj] = make_float4(xa0, xa1, xa2, xa3);

        const int yj = tid & 63, yq = tid >> 6;       // 8 k-chunks
        float ya0, ya1, ya2, ya3;
        ya0 = ya1 = ya2 = ya3 = (yq == 0) ? byr : 0.f;
#pragma unroll
        for (int i = 0; i < 4; i++) {                 // C2: 16 k per chunk
            int k4 = yq * 4 + i;
            float4 c = g_C2T4[k4 * NYDIM + yj];
            const float4* v = &xc[4 * k4];
            FMA4C(ya0, ya1, ya2, ya3, c.x, v[0]);
            FMA4C(ya0, ya1, ya2, ya3, c.y, v[1]);
            FMA4C(ya0, ya1, ya2, ya3, c.z, v[2]);
            FMA4C(ya0, ya1, ya2, ya3, c.w, v[3]);
        }
#pragma unroll 4
        for (int i = 0; i < 8; i++) {                 // D21: 32 k per chunk
            int k4 = yq * 8 + i;
            float4 c = g_D21T4[k4 * NYDIM + yj];
            const float4* v = &s.w[4 * k4];
            FMA4C(ya0, ya1, ya2, ya3, c.x, v[0]);
            FMA4C(ya0, ya1, ya2, ya3, c.y, v[1]);
            FMA4C(ya0, ya1, ya2, ya3, c.z, v[2]);
            FMA4C(ya0, ya1, ya2, ya3, c.w, v[3]);
        }
#pragma unroll
        for (int i = 0; i < 2; i++) {                 // D22: 8 k per chunk
            int k4 = yq * 2 + i;
            float4 c = g_D22T4[k4 * NYDIM + yj];
            const float4* v = &uc[4 * k4];
            FMA4C(ya0, ya1, ya2, ya3, c.x, v[0]);
            FMA4C(ya0, ya1, ya2, ya3, c.y, v[1]);
            FMA4C(ya0, ya1, ya2, ya3, c.z, v[2]);
            FMA4C(ya0, ya1, ya2, ya3, c.w, v[3]);
        }
        if (yq > 0) s.ypart[yq - 1][yj] = make_float4(ya0, ya1, ya2, ya3);
        __syncthreads();

        // ---- combines ----
        if (xq == 0) {
#pragma unroll
            for (int pq = 0; pq < 3; pq++) {
                float4 pp = s.xpart[pq][xj];
                xa0 += pp.x; xa1 += pp.y; xa2 += pp.z; xa3 += pp.w;
            }
            s.xk[nxt][xj] = make_float4(xa0, xa1, xa2, xa3);
        }
        if (yq == 0) {
#pragma unroll
            for (int pq = 0; pq < 7; pq++) {
                float4 pp = s.ypart[pq][yj];
                ya0 += pp.x; ya1 += pp.y; ya2 += pp.z; ya3 += pp.w;
            }
            float* yo = yout + ((size_t)t * BATCH + row0) * NYDIM + yj;
            yo[0 * NYDIM] = ya0;
            yo[1 * NYDIM] = ya1;
            yo[2 * NYDIM] = ya2;
            yo[3 * NYDIM] = ya3;
        }
        cur ^= 1;
    }

    // ---- final state x1 ----
    __syncthreads();
    if (tid < NXDIM) {
        float4 v = s.xk[cur][tid];
        out[(size_t)(row0 + 0) * NXDIM + tid] = v.x;
        out[(size_t)(row0 + 1) * NXDIM + tid] = v.y;
        out[(size_t)(row0 + 2) * NXDIM + tid] = v.z;
        out[(size_t)(row0 + 3) * NXDIM + tid] = v.w;
    }
}

extern "C" void kernel_launch(void* const* d_in, const int* in_sizes, int n_in,
                              void* d_out, int out_size)
{
    const float* x0  = (const float*)d_in[0];
    const float* u   = (const float*)d_in[1];
    const float* A   = (const float*)d_in[2];
    const float* B1  = (const float*)d_in[3];
    const float* B2  = (const float*)d_in[4];
    const float* C1  = (const float*)d_in[5];
    const float* C2  = (const float*)d_in[6];
    const float* D11 = (const float*)d_in[7];
    const float* D12 = (const float*)d_in[8];
    const float* D21 = (const float*)d_in[9];
    const float* D22 = (const float*)d_in[10];
    const float* bx  = (const float*)d_in[11];
    const float* bv  = (const float*)d_in[12];
    const float* by  = (const float*)d_in[13];
    float* out = (float*)d_out;

    prep_kernel<<<452, 256>>>(A, B1, B2, C1, C2, D11, D12, D21, D22);

    size_t smem = sizeof(Smem);
    cudaFuncSetAttribute(ren_kernel, cudaFuncAttributeMaxDynamicSharedMemorySize,
                         (int)smem);
    ren_kernel<<<NCTA, NTHR, smem>>>(x0, u, D11, bx, bv, by, out);
}